// round 4
// baseline (speedup 1.0000x reference)
#include <cuda_runtime.h>
#include <cuda_bf16.h>
#include <math_constants.h>

#define N_STATES   65536
#define LATENT     512
#define NCOL       (LATENT / 4)           // 128 float4 columns
#define NBLK       296                    // 2 blocks per SM on 148-SM GB300 -> all resident
#define WARPS_PB   8
#define NW         (NBLK * WARPS_PB)      // 2368 warps, grid-stride over rows

// ---- static scratch (no allocation allowed) ----
__device__ float              g_blk_m[NBLK];
__device__ float              g_blk_Z[NBLK];
__device__ float              g_blk_q[NBLK * LATENT];  // ~606 KB, L2-hot at combine time
__device__ unsigned long long g_sync = 0ULL;           // monotonic grid-sync ticket
__device__ unsigned           g_ctr  = 0;              // loss completion ticket (self-reset)

__device__ __forceinline__ unsigned long long ld_acq_u64(const unsigned long long* p) {
    unsigned long long v;
    asm volatile("ld.global.acquire.gpu.u64 %0, [%1];" : "=l"(v) : "l"(p));
    return v;
}

// ======================================================================
// Single fused persistent kernel:
//   phase 1: warp-per-row streaming (prefetched, evict-first loads),
//            online softmin, in-block fold -> 296 partials
//   grid sync (monotonic ticket; all blocks resident at occ=2)
//   phase 2: blocks 0..127 fold one float4 column each (L2-hot),
//            last block computes both losses
// ======================================================================
__global__ __launch_bounds__(256, 2)
void quant_fused(const float* __restrict__ imu,
                 const float* __restrict__ isg,
                 const float4* __restrict__ onst,   // row = 256 float4
                 float* __restrict__ out)           // [512 | 1 | 1 | 65536]
{
    // ---- shared memory (phases reuse disjoint arrays; budget ~24 KB) ----
    __shared__ float              s_m[WARPS_PB];
    __shared__ float              s_Z[WARPS_PB];
    __shared__ float              s_q[WARPS_PB][LATENT];   // 16 KB
    __shared__ unsigned long long s_epoch;
    __shared__ float              c_red[256];
    __shared__ float              c_f[NBLK];
    __shared__ float4             c_v[256];
    __shared__ int                c_last;

    const int lane = threadIdx.x & 31;
    const int wid  = threadIdx.x >> 5;
    const int t    = threadIdx.x;
    const int gw   = blockIdx.x * WARPS_PB + wid;
    float* dists_out = out + LATENT + 2;

    // per-lane input stats matching the float4 load layout:
    // float4 j covers d=2j (x:mu, y:sig) and d=2j+1 (z:mu, w:sig)
    float4 a[8];
#pragma unroll
    for (int k = 0; k < 8; k++) {
        int j  = lane + 32 * k;
        int d0 = 2 * j;
        a[k] = make_float4(imu[d0], isg[d0], imu[d0 + 1], isg[d0 + 1]);
    }

    float m = CUDART_INF_F;
    float Z = 0.f;
    float q[16];
#pragma unroll
    for (int i = 0; i < 16; i++) q[i] = 0.f;

    // ---------------- phase 1: prefetched streaming loop ----------------
    int row = gw;                          // gw < 2368 < N_STATES always
    float4 v[8];
    {
        const float4* p = onst + (size_t)row * 256 + lane;
#pragma unroll
        for (int k = 0; k < 8; k++) v[k] = __ldcs(p + 32 * k);
    }

    while (row < N_STATES) {
        const int  nrow   = row + NW;
        const bool nvalid = nrow < N_STATES;

        // prefetch next row (evict-first) while current row is processed
        float4 vn[8];
        if (nvalid) {
            const float4* pn = onst + (size_t)nrow * 256 + lane;
#pragma unroll
            for (int k = 0; k < 8; k++) vn[k] = __ldcs(pn + 32 * k);
        }

        float s = 0.f;
#pragma unroll
        for (int k = 0; k < 8; k++) {
            float dx = v[k].x - a[k].x; s = fmaf(dx, dx, s);
            float dy = v[k].y - a[k].y; s = fmaf(dy, dy, s);
            float dz = v[k].z - a[k].z; s = fmaf(dz, dz, s);
            float dw = v[k].w - a[k].w; s = fmaf(dw, dw, s);
        }
#pragma unroll
        for (int o = 16; o > 0; o >>= 1)
            s += __shfl_xor_sync(0xffffffffu, s, o);

        if (lane == 0) dists_out[row] = s;

        // online softmin: weights exp(m - d_i), m = running min
        float w;
        if (s < m) {
            float f = __expf(s - m);     // first row: exp(-inf) = 0
            Z *= f;
#pragma unroll
            for (int i = 0; i < 16; i++) q[i] *= f;
            m = s;
            w = 1.f;
        } else {
            w = __expf(m - s);
        }
        Z += w;
#pragma unroll
        for (int k = 0; k < 8; k++) {
            q[2 * k]     = fmaf(w, v[k].x, q[2 * k]);
            q[2 * k + 1] = fmaf(w, v[k].z, q[2 * k + 1]);
        }

        row = nrow;
#pragma unroll
        for (int k = 0; k < 8; k++) v[k] = vn[k];
    }

    // ---- in-block fold of 8 warp states -> one (m, Z, q[512]) partial ----
    if (lane == 0) s_m[wid] = m;
    __syncthreads();

    float mB = s_m[0];
#pragma unroll
    for (int w2 = 1; w2 < WARPS_PB; w2++) mB = fminf(mB, s_m[w2]);

    const float fw = __expf(mB - m);     // <= 1
    if (lane == 0) s_Z[wid] = Z * fw;
#pragma unroll
    for (int k = 0; k < 8; k++) {
        int j = lane + 32 * k;
        s_q[wid][2 * j]     = q[2 * k]     * fw;
        s_q[wid][2 * j + 1] = q[2 * k + 1] * fw;
    }
    __syncthreads();

#pragma unroll
    for (int h = 0; h < 2; h++) {
        int c = t + 256 * h;
        float acc = 0.f;
#pragma unroll
        for (int w2 = 0; w2 < WARPS_PB; w2++) acc += s_q[w2][c];
        g_blk_q[blockIdx.x * LATENT + c] = acc;
    }
    if (t == 0) {
        float zz = 0.f;
#pragma unroll
        for (int w2 = 0; w2 < WARPS_PB; w2++) zz += s_Z[w2];
        g_blk_Z[blockIdx.x] = zz;
        g_blk_m[blockIdx.x] = mB;
    }

    // ---------------- grid sync (monotonic, graph-replay safe) ----------------
    __threadfence();
    if (t == 0) {
        unsigned long long ticket = atomicAdd(&g_sync, 1ULL);
        s_epoch = ticket / NBLK;          // same value for all blocks this launch
    }
    __syncthreads();

    if (blockIdx.x >= NCOL) return;       // non-combining blocks done

    if (t == 0) {
        const unsigned long long target = (s_epoch + 1ULL) * NBLK;
        while (ld_acq_u64(&g_sync) < target) { }
    }
    __syncthreads();
    __threadfence();                       // acquire partials from all blocks

    // ---------------- phase 2: column-parallel combine (L2-hot) ----------------
    const int j = blockIdx.x;             // float4 column 0..127

    // global min over block mins (fixed-order tree: deterministic)
    float mv = CUDART_INF_F;
    for (int b = t; b < NBLK; b += 256) mv = fminf(mv, g_blk_m[b]);
    c_red[t] = mv;
    __syncthreads();
#pragma unroll
    for (int o = 128; o > 0; o >>= 1) {
        if (t < o) c_red[t] = fminf(c_red[t], c_red[t + o]);
        __syncthreads();
    }
    const float M = c_red[0];
    __syncthreads();

    // rescale factors + Z
    float zv = 0.f;
    for (int b = t; b < NBLK; b += 256) {
        float fb = __expf(M - g_blk_m[b]);
        c_f[b] = fb;
        zv = fmaf(g_blk_Z[b], fb, zv);
    }
    c_red[t] = zv;
    __syncthreads();
#pragma unroll
    for (int o = 128; o > 0; o >>= 1) {
        if (t < o) c_red[t] += c_red[t + o];
        __syncthreads();
    }
    const float Z2 = c_red[0];

    // fold this block's column over all partials
    const float4* q4 = (const float4*)g_blk_q;
    float4 acc = make_float4(0.f, 0.f, 0.f, 0.f);
    for (int b = t; b < NBLK; b += 256) {
        float  fb = c_f[b];
        float4 x  = q4[(size_t)b * NCOL + j];
        acc.x = fmaf(fb, x.x, acc.x);
        acc.y = fmaf(fb, x.y, acc.y);
        acc.z = fmaf(fb, x.z, acc.z);
        acc.w = fmaf(fb, x.w, acc.w);
    }
    c_v[t] = acc;
    __syncthreads();
#pragma unroll
    for (int o = 128; o > 0; o >>= 1) {
        if (t < o) {
            float4 a2 = c_v[t], b2 = c_v[t + o];
            a2.x += b2.x; a2.y += b2.y; a2.z += b2.z; a2.w += b2.w;
            c_v[t] = a2;
        }
        __syncthreads();
    }
    if (t == 0) {
        float4 r = c_v[0];
        ((float4*)out)[j] = make_float4(r.x / Z2, r.y / Z2, r.z / Z2, r.w / Z2);
    }

    // ---- last-block-done: losses from the finalized quantised vector ----
    __threadfence();
    if (t == 0) c_last = (atomicAdd(&g_ctr, 1u) == NCOL - 1);
    __syncthreads();

    if (c_last) {
        __threadfence();                  // acquire other blocks' out[] writes
        float e = 0.f;
        for (int d = t; d < LATENT; d += 256) {
            float qd   = __ldcg(&out[d]); // bypass L1: other SMs wrote these
            float diff = qd - imu[d];
            e = fmaf(diff, diff, e);
        }
        c_red[t] = e;
        __syncthreads();
#pragma unroll
        for (int o = 128; o > 0; o >>= 1) {
            if (t < o) c_red[t] += c_red[t + o];
            __syncthreads();
        }
        if (t == 0) {
            float loss = c_red[0] / (float)LATENT;
            out[LATENT]     = loss;   // loss_enc
            out[LATENT + 1] = loss;   // loss_ref (stop_gradient => same value)
            g_ctr = 0;                // reset for next graph replay
        }
    }
}

// ======================================================================
extern "C" void kernel_launch(void* const* d_in, const int* in_sizes, int n_in,
                              void* d_out, int out_size)
{
    const float*  imu  = (const float*)d_in[0];   // input_mu  [512]
    const float*  isg  = (const float*)d_in[1];   // input_sig [512]
    const float4* onst = (const float4*)d_in[2];  // on_states [65536,512,2]
    float* out = (float*)d_out;                   // [512 | 1 | 1 | 65536]

    quant_fused<<<NBLK, 256>>>(imu, isg, onst, out);
}

// round 5
// speedup vs baseline: 1.0344x; 1.0344x over previous
#include <cuda_runtime.h>
#include <cuda_bf16.h>
#include <math_constants.h>

#define N_STATES   65536
#define LATENT     512
#define NCOL       (LATENT / 4)           // 128 float4 columns
#define OCC        3
#define NBLK       (148 * OCC)            // 444 blocks, ALL resident (enforced by launch_bounds)
#define WARPS_PB   8
#define NW         (NBLK * WARPS_PB)      // 3552 warps, grid-stride over rows

// ---- static scratch (no allocation allowed) ----
__device__ float              g_blk_m[NBLK];
__device__ float              g_blk_Z[NBLK];
__device__ float              g_blk_q[NBLK * LATENT];  // ~909 KB, L2-hot at combine time
__device__ unsigned long long g_sync = 0ULL;           // monotonic grid-sync ticket
__device__ unsigned           g_ctr  = 0;              // loss completion ticket (self-reset)

__device__ __forceinline__ unsigned long long ld_acq_u64(const unsigned long long* p) {
    unsigned long long v;
    asm volatile("ld.global.acquire.gpu.u64 %0, [%1];" : "=l"(v) : "l"(p));
    return v;
}

// volatile LDS.128 — keeps the input-stats replica in shared memory instead of
// 32 registers (ptxas cannot hoist it back into the register file)
__device__ __forceinline__ float4 lds128v(const float4* smem_ptr) {
    float4 r;
    unsigned addr = (unsigned)__cvta_generic_to_shared(smem_ptr);
    asm volatile("ld.volatile.shared.v4.f32 {%0,%1,%2,%3}, [%4];"
                 : "=f"(r.x), "=f"(r.y), "=f"(r.z), "=f"(r.w) : "r"(addr));
    return r;
}

// ======================================================================
// Single fused persistent kernel, occupancy 3 (24 warps/SM):
//   phase 1: warp-per-row streaming (evict-first), online softmin,
//            in-block fold -> 444 partials
//   grid sync (monotonic ticket; all blocks resident)
//   phase 2: blocks 0..127 fold one float4 column each (L2-hot),
//            last block computes both losses
// ======================================================================
__global__ __launch_bounds__(256, OCC)
void quant_fused(const float* __restrict__ imu,
                 const float* __restrict__ isg,
                 const float4* __restrict__ onst,   // row = 256 float4
                 float* __restrict__ out)           // [512 | 1 | 1 | 65536]
{
    // ---- shared memory (~23.3 KB/block; 3 blocks/SM = 70 KB < 228 KB) ----
    __shared__ float4             s_a[8 * 32];             // 4 KB: input stats, [k*32+lane]
    __shared__ float              s_m[WARPS_PB];
    __shared__ float              s_Z[WARPS_PB];
    __shared__ float              s_q[WARPS_PB][LATENT];   // 16 KB
    __shared__ unsigned long long s_epoch;
    __shared__ float              c_red[256];
    __shared__ float              c_f[NBLK];               // 1.8 KB
    __shared__ int                c_last;

    const int lane = threadIdx.x & 31;
    const int wid  = threadIdx.x >> 5;
    const int t    = threadIdx.x;
    const int gw   = blockIdx.x * WARPS_PB + wid;
    float* dists_out = out + LATENT + 2;

    // build the per-lane input-stats replica ONCE per block, in shared:
    // entry [k*32+lane] covers float4 j=lane+32k -> d=2j (x:mu,y:sig), d=2j+1 (z:mu,w:sig)
    {
        int k2 = t >> 5, l2 = t & 31;
        int j  = l2 + 32 * k2;
        int d0 = 2 * j;
        s_a[k2 * 32 + l2] = make_float4(imu[d0], isg[d0], imu[d0 + 1], isg[d0 + 1]);
    }
    __syncthreads();

    float m = CUDART_INF_F;
    float Z = 0.f;
    float q[16];
#pragma unroll
    for (int i = 0; i < 16; i++) q[i] = 0.f;

    // ---------------- phase 1: streaming loop ----------------
    for (int row = gw; row < N_STATES; row += NW) {
        const float4* p = onst + (size_t)row * 256 + lane;
        float4 v[8];
#pragma unroll
        for (int k = 0; k < 8; k++) v[k] = __ldcs(p + 32 * k);

        float s = 0.f;
#pragma unroll
        for (int k = 0; k < 8; k++) {
            float4 ak = lds128v(&s_a[k * 32 + lane]);
            float dx = v[k].x - ak.x; s = fmaf(dx, dx, s);
            float dy = v[k].y - ak.y; s = fmaf(dy, dy, s);
            float dz = v[k].z - ak.z; s = fmaf(dz, dz, s);
            float dw = v[k].w - ak.w; s = fmaf(dw, dw, s);
        }
#pragma unroll
        for (int o = 16; o > 0; o >>= 1)
            s += __shfl_xor_sync(0xffffffffu, s, o);

        if (lane == 0) dists_out[row] = s;

        // online softmin: weights exp(m - d_i), m = running min
        float w;
        if (s < m) {
            float f = __expf(s - m);     // first row: exp(-inf) = 0
            Z *= f;
#pragma unroll
            for (int i = 0; i < 16; i++) q[i] *= f;
            m = s;
            w = 1.f;
        } else {
            w = __expf(m - s);
        }
        Z += w;
#pragma unroll
        for (int k = 0; k < 8; k++) {
            q[2 * k]     = fmaf(w, v[k].x, q[2 * k]);
            q[2 * k + 1] = fmaf(w, v[k].z, q[2 * k + 1]);
        }
    }

    // ---- in-block fold of 8 warp states -> one (m, Z, q[512]) partial ----
    if (lane == 0) s_m[wid] = m;
    __syncthreads();

    float mB = s_m[0];
#pragma unroll
    for (int w2 = 1; w2 < WARPS_PB; w2++) mB = fminf(mB, s_m[w2]);

    const float fw = __expf(mB - m);     // <= 1
    if (lane == 0) s_Z[wid] = Z * fw;
#pragma unroll
    for (int k = 0; k < 8; k++) {
        int j = lane + 32 * k;
        s_q[wid][2 * j]     = q[2 * k]     * fw;
        s_q[wid][2 * j + 1] = q[2 * k + 1] * fw;
    }
    __syncthreads();

#pragma unroll
    for (int h = 0; h < 2; h++) {
        int c = t + 256 * h;
        float acc = 0.f;
#pragma unroll
        for (int w2 = 0; w2 < WARPS_PB; w2++) acc += s_q[w2][c];
        g_blk_q[blockIdx.x * LATENT + c] = acc;
    }
    if (t == 0) {
        float zz = 0.f;
#pragma unroll
        for (int w2 = 0; w2 < WARPS_PB; w2++) zz += s_Z[w2];
        g_blk_Z[blockIdx.x] = zz;
        g_blk_m[blockIdx.x] = mB;
    }

    // ---------------- grid sync (monotonic, graph-replay safe) ----------------
    __threadfence();
    if (t == 0) {
        unsigned long long ticket = atomicAdd(&g_sync, 1ULL);
        s_epoch = ticket / NBLK;          // same value for all blocks this launch
    }
    __syncthreads();

    if (blockIdx.x >= NCOL) return;       // non-combining blocks done

    if (t == 0) {
        const unsigned long long target = (s_epoch + 1ULL) * NBLK;
        while (ld_acq_u64(&g_sync) < target) { }
    }
    __syncthreads();
    __threadfence();                       // acquire partials from all blocks

    // ---------------- phase 2: column-parallel combine (L2-hot) ----------------
    const int j = blockIdx.x;             // float4 column 0..127

    // global min over block mins (fixed-order tree: deterministic)
    float mv = CUDART_INF_F;
    for (int b = t; b < NBLK; b += 256) mv = fminf(mv, g_blk_m[b]);
    c_red[t] = mv;
    __syncthreads();
#pragma unroll
    for (int o = 128; o > 0; o >>= 1) {
        if (t < o) c_red[t] = fminf(c_red[t], c_red[t + o]);
        __syncthreads();
    }
    const float M = c_red[0];
    __syncthreads();

    // rescale factors + Z
    float zv = 0.f;
    for (int b = t; b < NBLK; b += 256) {
        float fb = __expf(M - g_blk_m[b]);
        c_f[b] = fb;
        zv = fmaf(g_blk_Z[b], fb, zv);
    }
    c_red[t] = zv;
    __syncthreads();
#pragma unroll
    for (int o = 128; o > 0; o >>= 1) {
        if (t < o) c_red[t] += c_red[t + o];
        __syncthreads();
    }
    const float Z2 = c_red[0];
    __syncthreads();

    // fold this block's column over all partials (reuse s_q as float4 scratch)
    float4* c_v = (float4*)&s_q[0][0];
    const float4* q4 = (const float4*)g_blk_q;
    float4 acc = make_float4(0.f, 0.f, 0.f, 0.f);
    for (int b = t; b < NBLK; b += 256) {
        float  fb = c_f[b];
        float4 x  = q4[(size_t)b * NCOL + j];
        acc.x = fmaf(fb, x.x, acc.x);
        acc.y = fmaf(fb, x.y, acc.y);
        acc.z = fmaf(fb, x.z, acc.z);
        acc.w = fmaf(fb, x.w, acc.w);
    }
    c_v[t] = acc;
    __syncthreads();
#pragma unroll
    for (int o = 128; o > 0; o >>= 1) {
        if (t < o) {
            float4 a2 = c_v[t], b2 = c_v[t + o];
            a2.x += b2.x; a2.y += b2.y; a2.z += b2.z; a2.w += b2.w;
            c_v[t] = a2;
        }
        __syncthreads();
    }
    if (t == 0) {
        float4 r = c_v[0];
        ((float4*)out)[j] = make_float4(r.x / Z2, r.y / Z2, r.z / Z2, r.w / Z2);
    }

    // ---- last-block-done: losses from the finalized quantised vector ----
    __threadfence();
    if (t == 0) c_last = (atomicAdd(&g_ctr, 1u) == NCOL - 1);
    __syncthreads();

    if (c_last) {
        __threadfence();                  // acquire other blocks' out[] writes
        float e = 0.f;
        for (int d = t; d < LATENT; d += 256) {
            float qd   = __ldcg(&out[d]); // bypass L1: other SMs wrote these
            float diff = qd - imu[d];
            e = fmaf(diff, diff, e);
        }
        c_red[t] = e;
        __syncthreads();
#pragma unroll
        for (int o = 128; o > 0; o >>= 1) {
            if (t < o) c_red[t] += c_red[t + o];
            __syncthreads();
        }
        if (t == 0) {
            float loss = c_red[0] / (float)LATENT;
            out[LATENT]     = loss;   // loss_enc
            out[LATENT + 1] = loss;   // loss_ref (stop_gradient => same value)
            g_ctr = 0;                // reset for next graph replay
        }
    }
}

// ======================================================================
extern "C" void kernel_launch(void* const* d_in, const int* in_sizes, int n_in,
                              void* d_out, int out_size)
{
    const float*  imu  = (const float*)d_in[0];   // input_mu  [512]
    const float*  isg  = (const float*)d_in[1];   // input_sig [512]
    const float4* onst = (const float4*)d_in[2];  // on_states [65536,512,2]
    float* out = (float*)d_out;                   // [512 | 1 | 1 | 65536]

    quant_fused<<<NBLK, 256>>>(imu, isg, onst, out);
}